// round 2
// baseline (speedup 1.0000x reference)
#include <cuda_runtime.h>
#include <math.h>

// ---------------------------------------------------------------------------
// ExpertChoiceRouter:
//   scores = sigmoid(x @ w)            [N], N = B*S = 16384, D = 2048
//   k = floor(N * 0.67) = 10977
//   top-k -> boolean mask (stable ties: lowest index wins, matching jax top_k)
//   aux = -mean(top_scores) * 1e-3
// Output (float32): out[0..N-1] = mask as 0/1, out[N] = aux loss.
// NOTE: current_mask is all-True by construction in the reference
// (static num_active) -> masking is a no-op; we ignore that input to avoid
// dtype-width ambiguity of bool buffers.
// ---------------------------------------------------------------------------

#define MAX_N 32768

__device__ float        g_logit[MAX_N];
__device__ unsigned int g_key[MAX_N];

// order-preserving float -> uint mapping (larger float => larger key)
__device__ __forceinline__ unsigned int f2key(float f) {
    unsigned int u = __float_as_uint(f);
    return (u & 0x80000000u) ? ~u : (u | 0x80000000u);
}
__device__ __forceinline__ float key2f(unsigned int k) {
    unsigned int u = (k & 0x80000000u) ? (k & 0x7FFFFFFFu) : ~k;
    return __uint_as_float(u);
}

// ---------------------------------------------------------------------------
// Kernel 1: GEMV. One warp per token row. Coalesced float4 loads of x;
// w (8KB) stays hot in L1/L2 via __ldg. HBM-bound: 128MB read.
// ---------------------------------------------------------------------------
__global__ void __launch_bounds__(256)
router_gemv_kernel(const float* __restrict__ x,
                   const float* __restrict__ w,
                   int N, int D) {
    int gwarp = (blockIdx.x * blockDim.x + threadIdx.x) >> 5;
    int lane  = threadIdx.x & 31;
    if (gwarp >= N) return;

    const float4* __restrict__ xr = reinterpret_cast<const float4*>(x + (size_t)gwarp * D);
    const float4* __restrict__ wv = reinterpret_cast<const float4*>(w);
    int nv = D >> 2;  // 512 float4 per row

    float acc = 0.f;
    #pragma unroll 4
    for (int i = lane; i < nv; i += 32) {
        float4 a = xr[i];
        float4 b = __ldg(&wv[i]);
        acc += a.x * b.x + a.y * b.y + a.z * b.z + a.w * b.w;
    }
    #pragma unroll
    for (int o = 16; o > 0; o >>= 1)
        acc += __shfl_down_sync(0xFFFFFFFFu, acc, o);

    if (lane == 0) {
        g_logit[gwarp] = acc;
        g_key[gwarp]   = f2key(acc);
    }
}

// ---------------------------------------------------------------------------
// Kernel 2: single-CTA radix select (MSB-first, 256 bins, 4 passes) +
// stable mask write + top-k sigmoid sum. All data L1-resident (64KB keys).
// ---------------------------------------------------------------------------
#define SEL_THREADS 1024

__global__ void __launch_bounds__(SEL_THREADS)
router_select_kernel(float* __restrict__ out, int N, int K, int out_size) {
    __shared__ unsigned int hist[256];
    __shared__ int   s_digit;
    __shared__ int   s_kr;
    __shared__ int   s_int[SEL_THREADS];
    __shared__ double s_dbl[SEL_THREADS];
    __shared__ int   s_scan[SEL_THREADS];
    __shared__ int   s_need_eq;

    const int tid = threadIdx.x;
    const int per = (N + SEL_THREADS - 1) / SEL_THREADS;   // 16
    const int i0  = tid * per;
    const int i1  = min(N, i0 + per);

    // ---- radix select: find key of the K-th largest value ----
    unsigned int prefix = 0, pmask = 0;
    int kr = K;   // 1-based rank among current candidates
    for (int shift = 24; shift >= 0; shift -= 8) {
        if (tid < 256) hist[tid] = 0;
        __syncthreads();
        for (int i = i0; i < i1; i++) {
            unsigned int k = g_key[i];
            if ((k & pmask) == prefix)
                atomicAdd(&hist[(k >> shift) & 0xFFu], 1u);
        }
        __syncthreads();
        if (tid == 0) {
            int cum = 0, d = 255;
            for (; d > 0; d--) {
                cum += (int)hist[d];
                if (cum >= kr) break;
            }
            if (cum < kr) cum += (int)hist[0];   // d == 0 fallthrough
            s_digit = d;
            s_kr    = kr - (cum - (int)hist[d]);
        }
        __syncthreads();
        prefix |= ((unsigned int)s_digit) << shift;
        pmask  |= (0xFFu << shift);
        kr = s_kr;
        __syncthreads();
    }
    const unsigned int tkey = prefix;
    const float        tval = key2f(tkey);

    // ---- per-thread: count greater / equal, sum sigmoid of strictly-greater ----
    int    cg_local  = 0;
    int    ceq_local = 0;
    double sum_local = 0.0;
    for (int i = i0; i < i1; i++) {
        unsigned int k = g_key[i];
        if (k > tkey) {
            cg_local++;
            float l = g_logit[i];
            sum_local += (double)(1.0f / (1.0f + __expf(-l)));
        } else if (k == tkey) {
            ceq_local++;
        }
    }

    // ---- reduce count_greater and sum ----
    s_int[tid] = cg_local;
    s_dbl[tid] = sum_local;
    __syncthreads();
    for (int s = SEL_THREADS >> 1; s > 0; s >>= 1) {
        if (tid < s) {
            s_int[tid] += s_int[tid + s];
            s_dbl[tid] += s_dbl[tid + s];
        }
        __syncthreads();
    }
    if (tid == 0) s_need_eq = K - s_int[0];
    const double sum_greater = s_dbl[0];

    // ---- exclusive scan of per-thread equal-counts (stable tie ordering) ----
    s_scan[tid] = ceq_local;
    __syncthreads();
    int val = ceq_local;
    for (int off = 1; off < SEL_THREADS; off <<= 1) {
        int add = (tid >= off) ? s_scan[tid - off] : 0;
        __syncthreads();
        s_scan[tid] = val = val + add;
        __syncthreads();
    }
    const int eq_base = s_scan[tid] - ceq_local;   // exclusive prefix
    const int need_eq = s_need_eq;

    // ---- write mask (chunks are contiguous index ranges -> stable) ----
    int r = eq_base;
    for (int i = i0; i < i1; i++) {
        unsigned int k = g_key[i];
        float m;
        if (k > tkey)       m = 1.0f;
        else if (k == tkey) { m = (r < need_eq) ? 1.0f : 0.0f; r++; }
        else                m = 0.0f;
        out[i] = m;
    }

    // ---- aux loss ----
    if (tid == 0 && out_size > N) {
        double sig_t = (double)(1.0f / (1.0f + __expf(-tval)));
        double total = sum_greater + (double)need_eq * sig_t;
        double aux   = -(total / (double)K) * 0.001;
        out[N] = (float)aux;
    }
}

// ---------------------------------------------------------------------------
extern "C" void kernel_launch(void* const* d_in, const int* in_sizes, int n_in,
                              void* d_out, int out_size) {
    const float* x = (const float*)d_in[0];
    const float* w = (const float*)d_in[2];
    float* out = (float*)d_out;

    const int N = in_sizes[1];            // B*S tokens (mask element count)
    const int D = in_sizes[2];            // d_model (router weight length)
    int K = (int)((double)N * 0.67);
    if (K < 1) K = 1;

    const int warpsPerBlock = 8;          // 256 threads
    const int blocks = (N + warpsPerBlock - 1) / warpsPerBlock;
    router_gemv_kernel<<<blocks, 256>>>(x, w, N, D);
    router_select_kernel<<<1, SEL_THREADS>>>(out, N, K, out_size);
}

// round 3
// speedup vs baseline: 1.1666x; 1.1666x over previous
#include <cuda_runtime.h>
#include <math.h>

// ---------------------------------------------------------------------------
// ExpertChoiceRouter: scores = sigmoid(x@w) [N=16384, D=2048];
// K = floor(N*0.67); top-K -> 0/1 mask (stable ties, lowest index first);
// out[N] = -mean(top_scores)*1e-3.
// current_mask is all-True by construction -> ignored.
// ---------------------------------------------------------------------------

#define MAX_N 32768
__device__ unsigned int g_key[MAX_N];

__device__ __forceinline__ unsigned int f2key(float f) {
    unsigned int u = __float_as_uint(f);
    return (u & 0x80000000u) ? ~u : (u | 0x80000000u);
}
__device__ __forceinline__ float key2f(unsigned int k) {
    unsigned int u = (k & 0x80000000u) ? (k & 0x7FFFFFFFu) : ~k;
    return __uint_as_float(u);
}

// ---------------------------------------------------------------------------
// Kernel 1: GEMV, one warp per row, fully unrolled (16 independent float4
// loads per lane -> deep MLP). HBM-bound: 128MB.
// ---------------------------------------------------------------------------
__global__ void __launch_bounds__(256)
router_gemv_kernel(const float* __restrict__ x,
                   const float* __restrict__ w,
                   int N, int D) {
    int gwarp = (blockIdx.x * blockDim.x + threadIdx.x) >> 5;
    int lane  = threadIdx.x & 31;
    if (gwarp >= N) return;

    const float4* __restrict__ xr = reinterpret_cast<const float4*>(x + (size_t)gwarp * D);
    const float4* __restrict__ wv = reinterpret_cast<const float4*>(w);
    const int nv = D >> 2;

    float acc = 0.f;
    #pragma unroll 16
    for (int i = lane; i < nv; i += 32) {
        float4 a = xr[i];
        float4 b = __ldg(&wv[i]);
        acc += a.x * b.x + a.y * b.y + a.z * b.z + a.w * b.w;
    }
    #pragma unroll
    for (int o = 16; o > 0; o >>= 1)
        acc += __shfl_down_sync(0xFFFFFFFFu, acc, o);

    if (lane == 0) g_key[gwarp] = f2key(acc);
}

// ---------------------------------------------------------------------------
// Kernel 2: single-CTA radix select. Per-warp private histograms kill the
// smem-atomic contention; parallel suffix-scan kills the serial digit scan.
// ---------------------------------------------------------------------------
#define SEL_THREADS 1024
#define NWARPS 32

__global__ void __launch_bounds__(SEL_THREADS)
router_select_kernel(float* __restrict__ out, int N, int K, int out_size) {
    __shared__ unsigned int whist[NWARPS][256];   // 32KB
    __shared__ unsigned int sufA[256], sufB[256];
    __shared__ int    s_digit, s_kr;
    __shared__ int    s_warp_i[NWARPS];
    __shared__ double s_warp_d[NWARPS];
    __shared__ int    s_warp_eq[NWARPS];
    __shared__ int    s_need_eq;
    __shared__ double s_sum_greater;

    const int tid  = threadIdx.x;
    const int wid  = tid >> 5;
    const int lane = tid & 31;
    const int per  = (N + SEL_THREADS - 1) / SEL_THREADS;   // 16
    const int i0   = tid * per;
    const int i1   = min(N, i0 + per);

    // ---- radix select: key of the K-th largest ----
    unsigned int prefix = 0, pmask = 0;
    int kr = K;
    for (int shift = 24; shift >= 0; shift -= 8) {
        for (int j = tid; j < NWARPS * 256; j += SEL_THREADS)
            ((unsigned int*)whist)[j] = 0;
        __syncthreads();

        for (int i = i0; i < i1; i++) {
            unsigned int k = g_key[i];
            if ((k & pmask) == prefix)
                atomicAdd(&whist[wid][(k >> shift) & 0xFFu], 1u);
        }
        __syncthreads();

        if (tid < 256) {
            unsigned int s = 0;
            #pragma unroll
            for (int w = 0; w < NWARPS; w++) s += whist[w][tid];
            sufA[tid] = s;
        }
        __syncthreads();

        // inclusive suffix scan: suf[i] = sum_{j>=i} hist[j]
        unsigned int* src = sufA;
        unsigned int* dst = sufB;
        for (int off = 1; off < 256; off <<= 1) {
            if (tid < 256) {
                unsigned int v = src[tid];
                if (tid + off < 256) v += src[tid + off];
                dst[tid] = v;
            }
            __syncthreads();
            unsigned int* t = src; src = dst; dst = t;
        }
        // largest d with suffix[d] >= kr  (exists: suffix[0] = #candidates >= kr)
        if (tid < 256) {
            int st    = (int)src[tid];
            int snext = (tid == 255) ? 0 : (int)src[tid + 1];
            if (st >= kr && snext < kr) { s_digit = tid; s_kr = kr - snext; }
        }
        __syncthreads();
        prefix |= ((unsigned int)s_digit) << shift;
        pmask  |= (0xFFu << shift);
        kr = s_kr;
        __syncthreads();
    }
    const unsigned int tkey = prefix;
    const float        tval = key2f(tkey);

    // ---- count greater/equal, sum sigmoid of strictly-greater ----
    int    cg  = 0;
    int    ceq = 0;
    double sum = 0.0;
    for (int i = i0; i < i1; i++) {
        unsigned int k = g_key[i];
        if (k > tkey) {
            cg++;
            float l = key2f(k);
            sum += (double)(1.0f / (1.0f + __expf(-l)));
        } else if (k == tkey) {
            ceq++;
        }
    }

    // warp-level: reduce cg & sum, inclusive scan of ceq
    int cg_r = cg; double sum_r = sum;
    #pragma unroll
    for (int o = 16; o > 0; o >>= 1) {
        cg_r  += __shfl_down_sync(0xFFFFFFFFu, cg_r, o);
        sum_r += __shfl_down_sync(0xFFFFFFFFu, sum_r, o);
    }
    int inc = ceq;
    #pragma unroll
    for (int o = 1; o < 32; o <<= 1) {
        int v = __shfl_up_sync(0xFFFFFFFFu, inc, o);
        if (lane >= o) inc += v;
    }
    if (lane == 31) s_warp_eq[wid] = inc;       // warp total of ceq
    if (lane == 0) { s_warp_i[wid] = cg_r; s_warp_d[wid] = sum_r; }
    __syncthreads();

    if (wid == 0) {
        int    ci = (lane < NWARPS) ? s_warp_i[lane] : 0;
        double cd = (lane < NWARPS) ? s_warp_d[lane] : 0.0;
        int    ce = (lane < NWARPS) ? s_warp_eq[lane] : 0;
        int ce_inc = ce;
        #pragma unroll
        for (int o = 1; o < 32; o <<= 1) {
            int v = __shfl_up_sync(0xFFFFFFFFu, ce_inc, o);
            if (lane >= o) ce_inc += v;
        }
        if (lane < NWARPS) s_warp_eq[lane] = ce_inc - ce;  // exclusive base per warp
        #pragma unroll
        for (int o = 16; o > 0; o >>= 1) {
            ci += __shfl_down_sync(0xFFFFFFFFu, ci, o);
            cd += __shfl_down_sync(0xFFFFFFFFu, cd, o);
        }
        if (lane == 0) { s_need_eq = K - ci; s_sum_greater = cd; }
    }
    __syncthreads();

    const int eq_base = s_warp_eq[wid] + (inc - ceq);   // global exclusive prefix
    const int need_eq = s_need_eq;

    // ---- write mask (contiguous per-thread chunks -> index-stable ties) ----
    int r = eq_base;
    for (int i = i0; i < i1; i++) {
        unsigned int k = g_key[i];
        float m;
        if (k > tkey)       m = 1.0f;
        else if (k == tkey) { m = (r < need_eq) ? 1.0f : 0.0f; r++; }
        else                m = 0.0f;
        out[i] = m;
    }

    // ---- aux loss ----
    if (tid == 0 && out_size > N) {
        double sig_t = (double)(1.0f / (1.0f + __expf(-tval)));
        double total = s_sum_greater + (double)need_eq * sig_t;
        out[N] = (float)(-(total / (double)K) * 0.001);
    }
}

// ---------------------------------------------------------------------------
extern "C" void kernel_launch(void* const* d_in, const int* in_sizes, int n_in,
                              void* d_out, int out_size) {
    const float* x = (const float*)d_in[0];
    const float* w = (const float*)d_in[2];
    float* out = (float*)d_out;

    const int N = in_sizes[1];
    const int D = in_sizes[2];
    int K = (int)((double)N * 0.67);
    if (K < 1) K = 1;

    const int blocks = (N + 7) / 8;   // 8 warps (rows) per 256-thread block
    router_gemv_kernel<<<blocks, 256>>>(x, w, N, D);
    router_select_kernel<<<1, SEL_THREADS>>>(out, N, K, out_size);
}

// round 4
// speedup vs baseline: 1.3639x; 1.1691x over previous
#include <cuda_runtime.h>
#include <math.h>

// ---------------------------------------------------------------------------
// ExpertChoiceRouter: scores = sigmoid(x@w) [N=16384, D=2048];
// K = floor(N*0.67); top-K -> 0/1 mask (stable ties, lowest index first);
// out[N] = -mean(top_scores)*1e-3.
// current_mask is all-True by construction -> ignored.
// ---------------------------------------------------------------------------

#define MAX_N 32768
__device__ unsigned int g_key[MAX_N];

__device__ __forceinline__ unsigned int f2key(float f) {
    unsigned int u = __float_as_uint(f);
    return (u & 0x80000000u) ? ~u : (u | 0x80000000u);
}
__device__ __forceinline__ float key2f(unsigned int k) {
    unsigned int u = (k & 0x80000000u) ? (k & 0x7FFFFFFFu) : ~k;
    return __uint_as_float(u);
}

// ---------------------------------------------------------------------------
// Kernel 1: GEMV, one warp per row. Streaming loads of x (read-once, 128MB),
// w stays hot in L1. HBM-bound.
// ---------------------------------------------------------------------------
__global__ void __launch_bounds__(256)
router_gemv_kernel(const float* __restrict__ x,
                   const float* __restrict__ w,
                   int N, int D) {
    int gwarp = (blockIdx.x * blockDim.x + threadIdx.x) >> 5;
    int lane  = threadIdx.x & 31;
    if (gwarp >= N) return;

    const float4* __restrict__ xr = reinterpret_cast<const float4*>(x + (size_t)gwarp * D);
    const float4* __restrict__ wv = reinterpret_cast<const float4*>(w);
    const int nv = D >> 2;

    float acc = 0.f;
    #pragma unroll 8
    for (int i = lane; i < nv; i += 32) {
        float4 a = __ldcs(&xr[i]);      // streaming: read-once data
        float4 b = __ldg(&wv[i]);       // 8KB, L1-resident
        acc += a.x * b.x + a.y * b.y + a.z * b.z + a.w * b.w;
    }
    #pragma unroll
    for (int o = 16; o > 0; o >>= 1)
        acc += __shfl_down_sync(0xFFFFFFFFu, acc, o);

    if (lane == 0) g_key[gwarp] = f2key(acc);
}

// ---------------------------------------------------------------------------
// Kernel 2: single-CTA radix select, atomic-free.
//   - match_any-based per-warp histograms (no ATOMS serialization)
//   - warp-0 shuffle suffix-scan over 256 bins (no barrier storm)
//   - keys L1-resident across the 4 passes
// ---------------------------------------------------------------------------
#define SEL_THREADS 1024
#define NW 32

__global__ void __launch_bounds__(SEL_THREADS)
router_select_kernel(float* __restrict__ out, int N, int K, int out_size) {
    __shared__ unsigned int whist[NW][256];   // 32KB, per-warp private
    __shared__ unsigned int sbin[256];        // merged histogram
    __shared__ int   s_digit, s_kr;
    __shared__ int   s_warp_i[NW];
    __shared__ float s_warp_f[NW];
    __shared__ int   s_warp_eq[NW];
    __shared__ int   s_need_eq;
    __shared__ float s_sum_greater;

    const int tid  = threadIdx.x;
    const int wid  = tid >> 5;
    const int lane = tid & 31;
    const int per  = (N + SEL_THREADS - 1) / SEL_THREADS;   // 16
    const int i0   = tid * per;
    const int i1   = min(N, i0 + per);

    // ---- radix select: key of the K-th largest ----
    unsigned int prefix = 0, pmask = 0;
    int kr = K;
    for (int shift = 24; shift >= 0; shift -= 8) {
        // zero per-warp hists (vectorized)
        {
            uint4 z = make_uint4(0u, 0u, 0u, 0u);
            uint4* p = reinterpret_cast<uint4*>(&whist[0][0]);
            #pragma unroll
            for (int j = tid; j < NW * 256 / 4; j += SEL_THREADS) p[j] = z;
        }
        __syncthreads();

        // histogram: match_any groups equal digits within the warp; the
        // leader lane does ONE plain add. Zero atomics.
        for (int i = i0; i < i1; i++) {
            unsigned int k = g_key[i];
            bool act = (k & pmask) == prefix;
            unsigned int d = act ? ((k >> shift) & 0xFFu) : 0x100u;
            unsigned int grp = __match_any_sync(0xFFFFFFFFu, d);
            if (act) {
                int leader = __ffs(grp) - 1;
                if (lane == leader) whist[wid][d] += (unsigned)__popc(grp);
            }
        }
        __syncthreads();

        // merge 32 warp hists -> sbin (lanes read consecutive bins: no conflicts)
        if (tid < 256) {
            unsigned int s = 0;
            #pragma unroll
            for (int w = 0; w < NW; w++) s += whist[w][tid];
            sbin[tid] = s;
        }
        __syncthreads();

        // warp 0: suffix scan + digit find, pure shuffles
        if (wid == 0) {
            unsigned int v[8], tot = 0;
            #pragma unroll
            for (int j = 0; j < 8; j++) { v[j] = sbin[lane * 8 + j]; tot += v[j]; }
            // inclusive suffix of lane totals
            unsigned int suf = tot;
            #pragma unroll
            for (int o = 1; o < 32; o <<= 1) {
                unsigned int t = __shfl_down_sync(0xFFFFFFFFu, suf, o);
                if (lane + o < 32) suf += t;
            }
            unsigned int Snext = suf - tot;   // suffix strictly after this lane's bins
            // walk this lane's 8 bins high->low; S is nonincreasing, so the
            // (S[b] >= kr && S[b+1] < kr) bin is unique chip-wide.
            #pragma unroll
            for (int j = 7; j >= 0; j--) {
                unsigned int Sb = Snext + v[j];
                if (Sb >= (unsigned)kr && Snext < (unsigned)kr) {
                    s_digit = lane * 8 + j;
                    s_kr    = kr - (int)Snext;
                }
                Snext = Sb;
            }
        }
        __syncthreads();
        prefix |= ((unsigned int)s_digit) << shift;
        pmask  |= (0xFFu << shift);
        kr = s_kr;
        __syncthreads();
    }
    const unsigned int tkey = prefix;
    const float        tval = key2f(tkey);

    // ---- count greater/equal, float sum of sigmoid(strictly-greater) ----
    int   cg  = 0;
    int   ceq = 0;
    float sum = 0.0f;
    for (int i = i0; i < i1; i++) {
        unsigned int k = g_key[i];
        if (k > tkey) {
            cg++;
            float l = key2f(k);
            sum += 1.0f / (1.0f + __expf(-l));
        } else if (k == tkey) {
            ceq++;
        }
    }

    // warp reduce cg & sum; warp inclusive scan of ceq
    int cg_r = cg; float sum_r = sum;
    #pragma unroll
    for (int o = 16; o > 0; o >>= 1) {
        cg_r  += __shfl_down_sync(0xFFFFFFFFu, cg_r, o);
        sum_r += __shfl_down_sync(0xFFFFFFFFu, sum_r, o);
    }
    int inc = ceq;
    #pragma unroll
    for (int o = 1; o < 32; o <<= 1) {
        int v = __shfl_up_sync(0xFFFFFFFFu, inc, o);
        if (lane >= o) inc += v;
    }
    if (lane == 31) s_warp_eq[wid] = inc;
    if (lane == 0) { s_warp_i[wid] = cg_r; s_warp_f[wid] = sum_r; }
    __syncthreads();

    if (wid == 0) {
        int   ci = (lane < NW) ? s_warp_i[lane] : 0;
        float cf = (lane < NW) ? s_warp_f[lane] : 0.0f;
        int   ce = (lane < NW) ? s_warp_eq[lane] : 0;
        int ce_inc = ce;
        #pragma unroll
        for (int o = 1; o < 32; o <<= 1) {
            int v = __shfl_up_sync(0xFFFFFFFFu, ce_inc, o);
            if (lane >= o) ce_inc += v;
        }
        if (lane < NW) s_warp_eq[lane] = ce_inc - ce;   // exclusive per-warp base
        #pragma unroll
        for (int o = 16; o > 0; o >>= 1) {
            ci += __shfl_down_sync(0xFFFFFFFFu, ci, o);
            cf += __shfl_down_sync(0xFFFFFFFFu, cf, o);
        }
        if (lane == 0) { s_need_eq = K - ci; s_sum_greater = cf; }
    }
    __syncthreads();

    const int need_eq = s_need_eq;
    int r = s_warp_eq[wid] + (inc - ceq);   // global exclusive prefix of equals

    // ---- write mask, float4-vectorized (per-thread chunk is contiguous) ----
    for (int i = i0; i < i1; i += 4) {
        float4 m;
        float* mp = &m.x;
        #pragma unroll
        for (int j = 0; j < 4; j++) {
            unsigned int k = g_key[i + j];
            float v;
            if (k > tkey)       v = 1.0f;
            else if (k == tkey) { v = (r < need_eq) ? 1.0f : 0.0f; r++; }
            else                v = 0.0f;
            mp[j] = v;
        }
        *reinterpret_cast<float4*>(&out[i]) = m;
    }

    // ---- aux loss ----
    if (tid == 0 && out_size > N) {
        float sig_t = 1.0f / (1.0f + __expf(-tval));
        float total = s_sum_greater + (float)need_eq * sig_t;
        out[N] = -(total / (float)K) * 0.001f;
    }
}

// ---------------------------------------------------------------------------
extern "C" void kernel_launch(void* const* d_in, const int* in_sizes, int n_in,
                              void* d_out, int out_size) {
    const float* x = (const float*)d_in[0];
    const float* w = (const float*)d_in[2];
    float* out = (float*)d_out;

    const int N = in_sizes[1];
    const int D = in_sizes[2];
    int K = (int)((double)N * 0.67);
    if (K < 1) K = 1;

    const int blocks = (N + 7) / 8;   // 8 warps (rows) per 256-thread block
    router_gemv_kernel<<<blocks, 256>>>(x, w, N, D);
    router_select_kernel<<<1, SEL_THREADS>>>(out, N, K, out_size);
}